// round 15
// baseline (speedup 1.0000x reference)
#include <cuda_runtime.h>
#include <cuda_fp16.h>
#include <cstdint>
#include <cfloat>

#define NMAX 100000
#define EMAX 1600000
#define NBIN (NMAX * 8)

// ---------------- scratch (static __device__, allocation-free) ----------------
__device__ __half g_NS[(size_t)NMAX * 832];  // fp16 [N][832]: [0:64]=n enc, [64+r*96..]=S sums
__device__ float  g_cat[(size_t)NMAX * 128]; // [N][128]: [0:64]=h2, [64:128]=o enc
__device__ float  g_h[(size_t)NMAX * 64];    // layer-1 output (fp32)
__device__ __half g_Mh[(size_t)NMAX * 576];  // [N][576] fp16: 0-511 = h@W2[r], 512-575 = h@Wroot2
__device__ float  g_t2[(size_t)NMAX * 64];   // relu(cat @ Wagg + bagg)
__device__ float  g_Wc1[832 * 64];           // [Wroot1 ; W1]
__device__ float  g_Wc2[64 * 576];           // [W2^T per-rel | Wroot2]
// CSR over (dst, r) bins: bin = dst*8 + r
__device__ int      g_cnt[NBIN + 8];         // padded for int4 scan
__device__ int      g_off[NBIN + 1];
__device__ int      g_coff[NBIN + 1];
__device__ unsigned g_meta[EMAX];            // src | (r<<17)
__device__ float2   g_ea2[EMAX];             // edge_attr per sorted slot

// ---------------- tf32 helpers ----------------
__device__ __forceinline__ unsigned f2tf(float f) {
    unsigned u; asm("cvt.rna.tf32.f32 %0, %1;" : "=r"(u) : "f"(f)); return u;
}
__device__ __forceinline__ void mma_tf32(float& c0, float& c1, float& c2, float& c3,
                                         unsigned a0, unsigned a1, unsigned a2, unsigned a3,
                                         unsigned b0, unsigned b1) {
    asm("mma.sync.aligned.m16n8k8.row.col.f32.tf32.tf32.f32 "
        "{%0,%1,%2,%3}, {%4,%5,%6,%7}, {%8,%9}, {%0,%1,%2,%3};"
        : "+f"(c0), "+f"(c1), "+f"(c2), "+f"(c3)
        : "r"(a0), "r"(a1), "r"(a2), "r"(a3), "r"(b0), "r"(b1));
}

// ---------------- CSR build over (dst,r) bins ----------------
__global__ void k_zero_cnt(int B) {
    int i = blockIdx.x * 256 + threadIdx.x;
    if (i < B + 8) g_cnt[i] = 0;
}
__global__ void k_hist(const int* __restrict__ ei, const int* __restrict__ et, int E) {
    int i = blockIdx.x * 256 + threadIdx.x;
    if (i < E) atomicAdd(&g_cnt[__ldg(ei + E + i) * 8 + __ldg(et + i)], 1);
}
// single-block scan over B bins; int4-vectorized sum phase (g_cnt zero-padded)
__global__ void __launch_bounds__(1024) k_scan(int B, int E) {
    __shared__ int sh[1024];
    int t = threadIdx.x;
    int chunk = ((B + 1023) / 1024 + 3) & ~3;   // multiple of 4
    int b = t * chunk;
    int eN = min(b + chunk, B);
    int s = 0;
    for (int i = b; i < eN; i += 4) {
        int4 v = *(const int4*)(g_cnt + i);
        s += v.x + v.y + v.z + v.w;
    }
    sh[t] = s;
    __syncthreads();
    for (int off = 1; off < 1024; off <<= 1) {
        int v = (t >= off) ? sh[t - off] : 0;
        __syncthreads();
        sh[t] += v;
        __syncthreads();
    }
    int run = (t == 0) ? 0 : sh[t - 1];
    for (int i = b; i < eN; i++) {
        int c = g_cnt[i];
        g_off[i] = run; g_coff[i] = run;
        run += c;
    }
    if (t == 0) { g_off[B] = E; g_coff[B] = E; }
}
__global__ void k_scatter(const int* __restrict__ ei, const float* __restrict__ ea,
                          const int* __restrict__ et, int E) {
    int i = blockIdx.x * 256 + threadIdx.x;
    if (i >= E) return;
    int dst = __ldg(ei + E + i);
    int src = __ldg(ei + i);
    int r   = __ldg(et + i);
    int pos = atomicAdd(&g_coff[dst * 8 + r], 1);
    g_meta[pos] = (unsigned)src | ((unsigned)r << 17);
    g_ea2[pos]  = make_float2(__ldg(ea + 2 * i), __ldg(ea + 2 * i + 1));
}

// ---------------- combined weights (832*64 = 53248 threads) ----------------
__global__ void k_prep(const float* __restrict__ Wroot1, const float* __restrict__ W1,
                       const float* __restrict__ W2, const float* __restrict__ Wroot2) {
    int i = blockIdx.x * 256 + threadIdx.x;
    if (i < 832 * 64) {
        int row = i >> 6, j = i & 63;
        g_Wc1[i] = (row < 64) ? Wroot1[row * 64 + j] : W1[(row - 64) * 64 + j];
    }
    if (i < 64 * 576) {
        int k = i / 576, c = i % 576;
        float v;
        if (c < 512) { int r = c >> 6, j = c & 63; v = W2[(r * 64 + k) * 64 + j]; }
        else         { v = Wroot2[k * 64 + (c - 512)]; }
        g_Wc2[i] = v;
    }
}

// ---------------- node encoders (n written fp16 into g_NS) ----------------
__global__ void k_encode(const float* __restrict__ x, const float* __restrict__ omega,
                         const float* __restrict__ Wn, const float* __restrict__ bn,
                         const float* __restrict__ Wo, const float* __restrict__ bo, int N) {
    int i = blockIdx.x * 256 + threadIdx.x;
    if (i >= N * 64) return;
    int d = i >> 6, j = i & 63;
    float x0 = __ldg(x + d * 3), x1 = __ldg(x + d * 3 + 1), x2 = __ldg(x + d * 3 + 2);
    float nv = fmaf(x0, __ldg(Wn + j), fmaf(x1, __ldg(Wn + 64 + j), fmaf(x2, __ldg(Wn + 128 + j), __ldg(bn + j))));
    g_NS[(size_t)d * 832 + j] = __float2half_rn(fmaxf(nv, 0.f));
    float o0 = __ldg(omega + d * 2), o1 = __ldg(omega + d * 2 + 1);
    float ov = fmaf(o0, __ldg(Wo + j), fmaf(o1, __ldg(Wo + 64 + j), __ldg(bo + j)));
    g_cat[(size_t)d * 128 + 64 + j] = fmaxf(ov, 0.f);
}

// ---------------- layer-1: warp per dst; r-sorted edges; running acc + uniform flush ----------------
__global__ void __launch_bounds__(256) k_edge1_csr(const float* __restrict__ We,
                                                   const float* __restrict__ be, int N) {
    int gw = (blockIdx.x * 256 + threadIdx.x) >> 5;
    if (gw >= N) return;
    int lane = threadIdx.x & 31;
    int start = __ldg(g_off + gw * 8), end = __ldg(g_off + gw * 8 + 8);

    float we0 = __ldg(We + lane), we1 = __ldg(We + 32 + lane), beL = __ldg(be + lane);
    __half* Sd = g_NS + (size_t)gw * 832 + 64;

    float a0 = 0.f, a1 = 0.f, aev = 0.f;
    int rcur = -1;

    auto store_rel = [&](int r, float v0, float v1, float ve) {
        *(__half2*)(Sd + r * 96 + lane * 2) = __floats2half2_rn(v0, v1);
        Sd[r * 96 + 64 + lane] = __float2half_rn(ve);
    };
    auto proc = [&](int r, float2 nv, float ev) {
        if (r != rcur) {                     // warp-uniform branch (r uniform per edge)
            if (rcur >= 0) store_rel(rcur, a0, a1, aev);
            for (int rz = rcur + 1; rz < r; rz++) store_rel(rz, 0.f, 0.f, 0.f);
            rcur = r; a0 = 0.f; a1 = 0.f; aev = 0.f;
        }
        a0 += nv.x; a1 += nv.y; aev += ev;
    };

    int e = start;
    for (; e + 4 <= end; e += 4) {
        unsigned mA = __ldg(g_meta + e),     mB = __ldg(g_meta + e + 1);
        unsigned mC = __ldg(g_meta + e + 2), mD = __ldg(g_meta + e + 3);
        float2 aA = __ldg(g_ea2 + e),     aB = __ldg(g_ea2 + e + 1);
        float2 aC = __ldg(g_ea2 + e + 2), aD = __ldg(g_ea2 + e + 3);
        float2 nA = __half22float2(*(const __half2*)(g_NS + (size_t)(mA & 0x1FFFFu) * 832 + lane * 2));
        float2 nB = __half22float2(*(const __half2*)(g_NS + (size_t)(mB & 0x1FFFFu) * 832 + lane * 2));
        float2 nC = __half22float2(*(const __half2*)(g_NS + (size_t)(mC & 0x1FFFFu) * 832 + lane * 2));
        float2 nD = __half22float2(*(const __half2*)(g_NS + (size_t)(mD & 0x1FFFFu) * 832 + lane * 2));
        float evA = fmaxf(fmaf(aA.x, we0, fmaf(aA.y, we1, beL)), 0.f);
        float evB = fmaxf(fmaf(aB.x, we0, fmaf(aB.y, we1, beL)), 0.f);
        float evC = fmaxf(fmaf(aC.x, we0, fmaf(aC.y, we1, beL)), 0.f);
        float evD = fmaxf(fmaf(aD.x, we0, fmaf(aD.y, we1, beL)), 0.f);
        proc((int)(mA >> 17), nA, evA);
        proc((int)(mB >> 17), nB, evB);
        proc((int)(mC >> 17), nC, evC);
        proc((int)(mD >> 17), nD, evD);
    }
    for (; e < end; e++) {
        unsigned mc = __ldg(g_meta + e);
        float2 ac = __ldg(g_ea2 + e);
        float2 nv = __half22float2(*(const __half2*)(g_NS + (size_t)(mc & 0x1FFFFu) * 832 + lane * 2));
        float ev = fmaxf(fmaf(ac.x, we0, fmaf(ac.y, we1, beL)), 0.f);
        proc((int)(mc >> 17), nv, ev);
    }
    // final flush: write current acc, zeros for remaining relations
    if (rcur >= 0) store_rel(rcur, a0, a1, aev);
    for (int rz = rcur + 1; rz < 8; rz++) store_rel(rz, 0.f, 0.f, 0.f);
}

// ---------------- layer-2: warp per dst; r-sorted edges; running max + uniform flush into sum ----------------
__global__ void __launch_bounds__(256) k_edge2_csr(const float* __restrict__ b2, int N) {
    int gw = (blockIdx.x * 256 + threadIdx.x) >> 5;
    if (gw >= N) return;
    int lane = threadIdx.x & 31;
    int start = __ldg(g_off + gw * 8), end = __ldg(g_off + gw * 8 + 8);

    float2 tmp = __half22float2(*(const __half2*)(g_Mh + (size_t)gw * 576 + 512 + lane * 2));
    float s0 = tmp.x + __ldg(b2 + lane * 2);
    float s1 = tmp.y + __ldg(b2 + lane * 2 + 1);

    float m0v = 0.f, m1v = 0.f;
    int rcur = -1;

    auto proc = [&](int r, float2 mv) {
        if (r != rcur) {                     // warp-uniform
            if (rcur >= 0) { s0 += m0v; s1 += m1v; }
            rcur = r; m0v = mv.x; m1v = mv.y;
        } else {
            m0v = fmaxf(m0v, mv.x); m1v = fmaxf(m1v, mv.y);
        }
    };

    int e = start;
    for (; e + 4 <= end; e += 4) {
        unsigned mA = __ldg(g_meta + e),     mB = __ldg(g_meta + e + 1);
        unsigned mC = __ldg(g_meta + e + 2), mD = __ldg(g_meta + e + 3);
        int rA = (int)(mA >> 17), rB = (int)(mB >> 17);
        int rC = (int)(mC >> 17), rD = (int)(mD >> 17);
        float2 vA = __half22float2(*(const __half2*)(g_Mh + (size_t)(mA & 0x1FFFFu) * 576 + rA * 64 + lane * 2));
        float2 vB = __half22float2(*(const __half2*)(g_Mh + (size_t)(mB & 0x1FFFFu) * 576 + rB * 64 + lane * 2));
        float2 vC = __half22float2(*(const __half2*)(g_Mh + (size_t)(mC & 0x1FFFFu) * 576 + rC * 64 + lane * 2));
        float2 vD = __half22float2(*(const __half2*)(g_Mh + (size_t)(mD & 0x1FFFFu) * 576 + rD * 64 + lane * 2));
        proc(rA, vA); proc(rB, vB); proc(rC, vC); proc(rD, vD);
    }
    for (; e < end; e++) {
        unsigned mc = __ldg(g_meta + e);
        int r = (int)(mc >> 17);
        float2 mv = __half22float2(*(const __half2*)(g_Mh + (size_t)(mc & 0x1FFFFu) * 576 + r * 64 + lane * 2));
        proc(r, mv);
    }
    if (rcur >= 0) { s0 += m0v; s1 += m1v; }
    *(float2*)(g_cat + (size_t)gw * 128 + lane * 2) = make_float2(fmaxf(s0, 0.f), fmaxf(s1, 0.f));
}

// ---------------- tf32 tensor GEMM: C[M,cols] = A[M,K] @ B[K,cols] (+bias, relu) ----------------
// HIN: 0 = fp32 A, 1 = fp16 A.  HOUT: 0 = fp32 C, 1 = fp16 C.
template <int HIN, int HOUT>
__global__ void __launch_bounds__(256) k_gemm_tf32(
    const void* __restrict__ Ain, int lda, int K,
    const float* __restrict__ B, int ldb,
    const float* __restrict__ bias, int relu,
    void* __restrict__ Cout, int ldc, int M)
{
    __shared__ __align__(16) unsigned As[128 * 20];
    __shared__ __align__(16) unsigned Bs[64 * 20];
    int tid = threadIdx.x;
    int wid = tid >> 5, lane = tid & 31;
    int lk = lane & 3;
    int lr = lane >> 2;
    int row0 = blockIdx.x * 128;
    int col0 = blockIdx.y * 64;
    int wm = wid * 16;
    float acc[8][4];
#pragma unroll
    for (int t = 0; t < 8; t++)
#pragma unroll
        for (int i = 0; i < 4; i++) acc[t][i] = 0.f;

    for (int kc = 0; kc < K; kc += 16) {
#pragma unroll
        for (int it = 0; it < 2; it++) {
            int idx = tid + it * 256;
            int r = idx >> 2, kk = (idx & 3) * 4;
            int grow = row0 + r;
            float4 v = make_float4(0.f, 0.f, 0.f, 0.f);
            if (grow < M) {
                if (HIN) {
                    const __half* Ah = (const __half*)Ain;
                    uint2 raw = *(const uint2*)(Ah + (size_t)grow * lda + kc + kk);
                    float2 f0 = __half22float2(*(__half2*)&raw.x);
                    float2 f1 = __half22float2(*(__half2*)&raw.y);
                    v = make_float4(f0.x, f0.y, f1.x, f1.y);
                } else {
                    v = *(const float4*)((const float*)Ain + (size_t)grow * lda + kc + kk);
                }
            }
            uint4 u = make_uint4(f2tf(v.x), f2tf(v.y), f2tf(v.z), f2tf(v.w));
            *(uint4*)&As[r * 20 + kk] = u;
        }
        {
            int r = tid >> 4, cc = (tid & 15) * 4;
            float4 v = *(const float4*)(B + (size_t)(kc + r) * ldb + col0 + cc);
            Bs[(cc + 0) * 20 + r] = f2tf(v.x);
            Bs[(cc + 1) * 20 + r] = f2tf(v.y);
            Bs[(cc + 2) * 20 + r] = f2tf(v.z);
            Bs[(cc + 3) * 20 + r] = f2tf(v.w);
        }
        __syncthreads();
#pragma unroll
        for (int ks = 0; ks < 16; ks += 8) {
            unsigned a0 = As[(wm + lr) * 20 + ks + lk];
            unsigned a1 = As[(wm + 8 + lr) * 20 + ks + lk];
            unsigned a2 = As[(wm + lr) * 20 + ks + 4 + lk];
            unsigned a3 = As[(wm + 8 + lr) * 20 + ks + 4 + lk];
#pragma unroll
            for (int t = 0; t < 8; t++) {
                unsigned b0 = Bs[(t * 8 + lr) * 20 + ks + lk];
                unsigned b1 = Bs[(t * 8 + lr) * 20 + ks + 4 + lk];
                mma_tf32(acc[t][0], acc[t][1], acc[t][2], acc[t][3], a0, a1, a2, a3, b0, b1);
            }
        }
        __syncthreads();
    }
    int r0 = row0 + wm + lr;
    int r1 = r0 + 8;
#pragma unroll
    for (int t = 0; t < 8; t++) {
        int c = col0 + t * 8 + 2 * lk;
        float2 v0 = make_float2(acc[t][0], acc[t][1]);
        float2 v1 = make_float2(acc[t][2], acc[t][3]);
        if (bias) {
            float2 bb = *(const float2*)(bias + (c - col0));
            v0.x += bb.x; v0.y += bb.y; v1.x += bb.x; v1.y += bb.y;
        }
        if (relu) {
            v0.x = fmaxf(v0.x, 0.f); v0.y = fmaxf(v0.y, 0.f);
            v1.x = fmaxf(v1.x, 0.f); v1.y = fmaxf(v1.y, 0.f);
        }
        if (HOUT) {
            __half* C = (__half*)Cout;
            if (r0 < M) *(__half2*)(C + (size_t)r0 * ldc + c) = __floats2half2_rn(v0.x, v0.y);
            if (r1 < M) *(__half2*)(C + (size_t)r1 * ldc + c) = __floats2half2_rn(v1.x, v1.y);
        } else {
            float* C = (float*)Cout;
            if (r0 < M) *(float2*)(C + (size_t)r0 * ldc + c) = v0;
            if (r1 < M) *(float2*)(C + (size_t)r1 * ldc + c) = v1;
        }
    }
}

// ---------------- head: out = tanh(t2 . Wc + bc) * 5 ----------------
__global__ void k_f4(const float* __restrict__ Wc, const float* __restrict__ bc,
                     float* __restrict__ out, int N) {
    int w = (blockIdx.x * blockDim.x + threadIdx.x) >> 5;
    if (w >= N) return;
    int lane = threadIdx.x & 31;
    const float* t = g_t2 + (size_t)w * 64;
    float p = t[lane] * __ldg(Wc + lane) + t[lane + 32] * __ldg(Wc + lane + 32);
#pragma unroll
    for (int off = 16; off > 0; off >>= 1) p += __shfl_xor_sync(0xffffffffu, p, off);
    if (lane == 0) out[w] = tanhf(p + __ldg(bc)) * 5.f;
}

extern "C" void kernel_launch(void* const* d_in, const int* in_sizes, int n_in,
                              void* d_out, int out_size) {
    const float* x      = (const float*)d_in[0];
    const int*   ei     = (const int*)  d_in[1];
    const float* ea     = (const float*)d_in[2];
    const int*   et     = (const int*)  d_in[3];
    const float* omega  = (const float*)d_in[4];
    const float* Wn     = (const float*)d_in[5];
    const float* bn     = (const float*)d_in[6];
    const float* We     = (const float*)d_in[7];
    const float* be     = (const float*)d_in[8];
    const float* Wo     = (const float*)d_in[9];
    const float* bo     = (const float*)d_in[10];
    const float* W1     = (const float*)d_in[11];
    const float* Wroot1 = (const float*)d_in[12];
    const float* b1     = (const float*)d_in[13];
    const float* W2     = (const float*)d_in[14];
    const float* Wroot2 = (const float*)d_in[15];
    const float* b2     = (const float*)d_in[16];
    const float* Wagg   = (const float*)d_in[17];
    const float* bagg   = (const float*)d_in[18];
    const float* Wc     = (const float*)d_in[19];
    const float* bc     = (const float*)d_in[20];
    float* out = (float*)d_out;

    int N = in_sizes[0] / 3;
    int E = in_sizes[3];
    if (N > NMAX) N = NMAX;
    if (E > EMAX) E = EMAX;
    int B = N * 8;

    __half *pNS, *pMh;
    float *ph, *pcat, *pt2, *pWc1, *pWc2;
    cudaGetSymbolAddress((void**)&pNS,  g_NS);
    cudaGetSymbolAddress((void**)&ph,   g_h);
    cudaGetSymbolAddress((void**)&pMh,  g_Mh);
    cudaGetSymbolAddress((void**)&pcat, g_cat);
    cudaGetSymbolAddress((void**)&pt2,  g_t2);
    cudaGetSymbolAddress((void**)&pWc1, g_Wc1);
    cudaGetSymbolAddress((void**)&pWc2, g_Wc2);

    // ---- CSR build over (dst,r) bins + encode ----
    k_zero_cnt<<<(B + 8 + 255) / 256, 256>>>(B);
    k_hist<<<(E + 255) / 256, 256>>>(ei, et, E);
    k_scan<<<1, 1024>>>(B, E);
    k_encode<<<(N * 64 + 255) / 256, 256>>>(x, omega, Wn, bn, Wo, bo, N);
    k_scatter<<<(E + 255) / 256, 256>>>(ei, ea, et, E);
    // ---- layer 1 ----
    k_edge1_csr<<<(N * 32 + 255) / 256, 256>>>(We, be, N);
    k_prep<<<(832 * 64 + 255) / 256, 256>>>(Wroot1, W1, W2, Wroot2);
    k_gemm_tf32<1, 0><<<dim3((N + 127) / 128, 1), 256>>>(pNS, 832, 832, pWc1, 64, b1, 1, ph, 64, N);
    // ---- layer 2 (M written as fp16) ----
    k_gemm_tf32<0, 1><<<dim3((N + 127) / 128, 9), 256>>>(ph, 64, 64, pWc2, 576, nullptr, 0, pMh, 576, N);
    k_edge2_csr<<<(N * 32 + 255) / 256, 256>>>(b2, N);
    // ---- head (tf32; grid.y = 1) ----
    k_gemm_tf32<0, 0><<<dim3((N + 127) / 128, 1), 256>>>(pcat, 128, 128, Wagg, 64, bagg, 1, pt2, 64, N);
    k_f4<<<(N + 7) / 8, 256>>>(Wc, bc, out, N);
}

// round 16
// speedup vs baseline: 2.5139x; 2.5139x over previous
#include <cuda_runtime.h>
#include <cuda_fp16.h>
#include <cstdint>
#include <cfloat>

#define NMAX 100000
#define EMAX 1600000

// ---------------- scratch (static __device__, allocation-free) ----------------
__device__ float  g_NS[(size_t)NMAX * 832];  // [N][832]: [0:64]=n enc (fp32, GEMM A), [64+r*96..]=S sums
__device__ __half g_nh[(size_t)NMAX * 64];   // n enc in fp16 (edge1 gather source)
__device__ float  g_cat[(size_t)NMAX * 128]; // [N][128]: [0:64]=h2, [64:128]=o enc
__device__ float  g_h[(size_t)NMAX * 64];    // layer-1 output
__device__ __half g_Mh[(size_t)NMAX * 576];  // [N][576] fp16: 0-511 = h@W2[r], 512-575 = h@Wroot2
__device__ float  g_t2[(size_t)NMAX * 64];   // relu(cat @ Wagg + bagg)
__device__ float  g_Wc1[832 * 64];           // [Wroot1 ; W1]
__device__ float  g_Wc2[64 * 576];           // [W2^T per-rel | Wroot2]
// CSR (per-dst, round-13 proven)
__device__ int      g_cnt[NMAX + 1];
__device__ int      g_off[NMAX + 1];
__device__ int      g_coff[NMAX + 1];
__device__ unsigned g_meta[EMAX];            // src | (r<<17)
__device__ float2   g_ea2[EMAX];             // edge_attr per sorted slot

// ---------------- tf32 helpers ----------------
__device__ __forceinline__ unsigned f2tf(float f) {
    unsigned u; asm("cvt.rna.tf32.f32 %0, %1;" : "=r"(u) : "f"(f)); return u;
}
__device__ __forceinline__ void mma_tf32(float& c0, float& c1, float& c2, float& c3,
                                         unsigned a0, unsigned a1, unsigned a2, unsigned a3,
                                         unsigned b0, unsigned b1) {
    asm("mma.sync.aligned.m16n8k8.row.col.f32.tf32.tf32.f32 "
        "{%0,%1,%2,%3}, {%4,%5,%6,%7}, {%8,%9}, {%0,%1,%2,%3};"
        : "+f"(c0), "+f"(c1), "+f"(c2), "+f"(c3)
        : "r"(a0), "r"(a1), "r"(a2), "r"(a3), "r"(b0), "r"(b1));
}

// ---------------- CSR build (round-13 proven) ----------------
__global__ void k_zero_cnt(int N) {
    int i = blockIdx.x * 256 + threadIdx.x;
    if (i <= N) g_cnt[i] = 0;
}
__global__ void k_hist(const int* __restrict__ ei, int E) {
    int i = blockIdx.x * 256 + threadIdx.x;
    if (i < E) atomicAdd(&g_cnt[__ldg(ei + E + i)], 1);
}
__global__ void __launch_bounds__(1024) k_scan(int N, int E) {
    __shared__ int sh[1024];
    int t = threadIdx.x;
    int chunk = (N + 1023) / 1024;
    int b = t * chunk, eN = min(b + chunk, N);
    int s = 0;
    for (int i = b; i < eN; i++) s += g_cnt[i];
    sh[t] = s;
    __syncthreads();
    for (int off = 1; off < 1024; off <<= 1) {
        int v = (t >= off) ? sh[t - off] : 0;
        __syncthreads();
        sh[t] += v;
        __syncthreads();
    }
    int run = (t == 0) ? 0 : sh[t - 1];
    for (int i = b; i < eN; i++) {
        int c = g_cnt[i];
        g_off[i] = run; g_coff[i] = run;
        run += c;
    }
    if (t == 0) { g_off[N] = E; g_coff[N] = E; }
}
__global__ void k_scatter(const int* __restrict__ ei, const float* __restrict__ ea,
                          const int* __restrict__ et, int E) {
    int i = blockIdx.x * 256 + threadIdx.x;
    if (i >= E) return;
    int dst = __ldg(ei + E + i);
    int src = __ldg(ei + i);
    int r   = __ldg(et + i);
    int pos = atomicAdd(&g_coff[dst], 1);
    g_meta[pos] = (unsigned)src | ((unsigned)r << 17);
    g_ea2[pos]  = make_float2(__ldg(ea + 2 * i), __ldg(ea + 2 * i + 1));
}

// ---------------- combined weights (832*64 = 53248 threads) ----------------
__global__ void k_prep(const float* __restrict__ Wroot1, const float* __restrict__ W1,
                       const float* __restrict__ W2, const float* __restrict__ Wroot2) {
    int i = blockIdx.x * 256 + threadIdx.x;
    if (i < 832 * 64) {
        int row = i >> 6, j = i & 63;
        g_Wc1[i] = (row < 64) ? Wroot1[row * 64 + j] : W1[(row - 64) * 64 + j];
    }
    if (i < 64 * 576) {
        int k = i / 576, c = i % 576;
        float v;
        if (c < 512) { int r = c >> 6, j = c & 63; v = W2[(r * 64 + k) * 64 + j]; }
        else         { v = Wroot2[k * 64 + (c - 512)]; }
        g_Wc2[i] = v;
    }
}

// ---------------- node encoders (dual write: fp32 for GEMM A, fp16 for edge gather) ----------------
__global__ void k_encode(const float* __restrict__ x, const float* __restrict__ omega,
                         const float* __restrict__ Wn, const float* __restrict__ bn,
                         const float* __restrict__ Wo, const float* __restrict__ bo, int N) {
    int i = blockIdx.x * 256 + threadIdx.x;
    if (i >= N * 64) return;
    int d = i >> 6, j = i & 63;
    float x0 = __ldg(x + d * 3), x1 = __ldg(x + d * 3 + 1), x2 = __ldg(x + d * 3 + 2);
    float nv = fmaf(x0, __ldg(Wn + j), fmaf(x1, __ldg(Wn + 64 + j), fmaf(x2, __ldg(Wn + 128 + j), __ldg(bn + j))));
    nv = fmaxf(nv, 0.f);
    g_NS[(size_t)d * 832 + j] = nv;
    g_nh[(size_t)d * 64 + j] = __float2half_rn(nv);
    float o0 = __ldg(omega + d * 2), o1 = __ldg(omega + d * 2 + 1);
    float ov = fmaf(o0, __ldg(Wo + j), fmaf(o1, __ldg(Wo + 64 + j), __ldg(bo + j)));
    g_cat[(size_t)d * 128 + 64 + j] = fmaxf(ov, 0.f);
}

// ---------------- layer-1: warp per dst; chunk-4 straight-line; fp16 gathers (round-13 proven) ----------------
__global__ void __launch_bounds__(256) k_edge1_csr(const float* __restrict__ We,
                                                   const float* __restrict__ be, int N) {
    int gw = (blockIdx.x * 256 + threadIdx.x) >> 5;
    if (gw >= N) return;
    int lane = threadIdx.x & 31;
    int start = __ldg(g_off + gw), end = __ldg(g_off + gw + 1);

    float we0 = __ldg(We + lane), we1 = __ldg(We + 32 + lane), beL = __ldg(be + lane);
    float an0[8], an1[8], ae[8];
#pragma unroll
    for (int rr = 0; rr < 8; rr++) { an0[rr] = 0.f; an1[rr] = 0.f; ae[rr] = 0.f; }

    int e = start;
    for (; e + 4 <= end; e += 4) {
        unsigned mA = __ldg(g_meta + e),     mB = __ldg(g_meta + e + 1);
        unsigned mC = __ldg(g_meta + e + 2), mD = __ldg(g_meta + e + 3);
        float2 aA = __ldg(g_ea2 + e),     aB = __ldg(g_ea2 + e + 1);
        float2 aC = __ldg(g_ea2 + e + 2), aD = __ldg(g_ea2 + e + 3);
        float2 nA = __half22float2(*(const __half2*)(g_nh + (size_t)(mA & 0x1FFFFu) * 64 + lane * 2));
        float2 nB = __half22float2(*(const __half2*)(g_nh + (size_t)(mB & 0x1FFFFu) * 64 + lane * 2));
        float2 nC = __half22float2(*(const __half2*)(g_nh + (size_t)(mC & 0x1FFFFu) * 64 + lane * 2));
        float2 nD = __half22float2(*(const __half2*)(g_nh + (size_t)(mD & 0x1FFFFu) * 64 + lane * 2));
        float evA = fmaxf(fmaf(aA.x, we0, fmaf(aA.y, we1, beL)), 0.f);
        float evB = fmaxf(fmaf(aB.x, we0, fmaf(aB.y, we1, beL)), 0.f);
        float evC = fmaxf(fmaf(aC.x, we0, fmaf(aC.y, we1, beL)), 0.f);
        float evD = fmaxf(fmaf(aD.x, we0, fmaf(aD.y, we1, beL)), 0.f);
        int rA = (int)(mA >> 17), rB = (int)(mB >> 17);
        int rC = (int)(mC >> 17), rD = (int)(mD >> 17);
#pragma unroll
        for (int rr = 0; rr < 8; rr++) {
            if (rA == rr) { an0[rr] += nA.x; an1[rr] += nA.y; ae[rr] += evA; }
            if (rB == rr) { an0[rr] += nB.x; an1[rr] += nB.y; ae[rr] += evB; }
            if (rC == rr) { an0[rr] += nC.x; an1[rr] += nC.y; ae[rr] += evC; }
            if (rD == rr) { an0[rr] += nD.x; an1[rr] += nD.y; ae[rr] += evD; }
        }
    }
    for (; e < end; e++) {
        unsigned mc = __ldg(g_meta + e);
        float2 ac = __ldg(g_ea2 + e);
        float2 nv = __half22float2(*(const __half2*)(g_nh + (size_t)(mc & 0x1FFFFu) * 64 + lane * 2));
        float ev = fmaxf(fmaf(ac.x, we0, fmaf(ac.y, we1, beL)), 0.f);
        int r = (int)(mc >> 17);
#pragma unroll
        for (int rr = 0; rr < 8; rr++) {
            if (r == rr) { an0[rr] += nv.x; an1[rr] += nv.y; ae[rr] += ev; }
        }
    }
    float* Sd = g_NS + (size_t)gw * 832 + 64;
#pragma unroll
    for (int rr = 0; rr < 8; rr++) {
        *(float2*)(Sd + rr * 96 + lane * 2) = make_float2(an0[rr], an1[rr]);
        Sd[rr * 96 + 64 + lane] = ae[rr];
    }
}

// ---------------- layer-2: warp per dst; chunk-4; fp16 gathers; fused combine (round-13 proven) ----------------
__global__ void __launch_bounds__(256) k_edge2_csr(const float* __restrict__ b2, int N) {
    int gw = (blockIdx.x * 256 + threadIdx.x) >> 5;
    if (gw >= N) return;
    int lane = threadIdx.x & 31;
    int start = __ldg(g_off + gw), end = __ldg(g_off + gw + 1);

    float m0[8], m1[8];
#pragma unroll
    for (int rr = 0; rr < 8; rr++) { m0[rr] = -FLT_MAX; m1[rr] = -FLT_MAX; }
    unsigned seen = 0;

    int e = start;
    for (; e + 4 <= end; e += 4) {
        unsigned mA = __ldg(g_meta + e),     mB = __ldg(g_meta + e + 1);
        unsigned mC = __ldg(g_meta + e + 2), mD = __ldg(g_meta + e + 3);
        int rA = (int)(mA >> 17), rB = (int)(mB >> 17);
        int rC = (int)(mC >> 17), rD = (int)(mD >> 17);
        float2 vA = __half22float2(*(const __half2*)(g_Mh + (size_t)(mA & 0x1FFFFu) * 576 + rA * 64 + lane * 2));
        float2 vB = __half22float2(*(const __half2*)(g_Mh + (size_t)(mB & 0x1FFFFu) * 576 + rB * 64 + lane * 2));
        float2 vC = __half22float2(*(const __half2*)(g_Mh + (size_t)(mC & 0x1FFFFu) * 576 + rC * 64 + lane * 2));
        float2 vD = __half22float2(*(const __half2*)(g_Mh + (size_t)(mD & 0x1FFFFu) * 576 + rD * 64 + lane * 2));
        seen |= (1u << rA) | (1u << rB) | (1u << rC) | (1u << rD);
#pragma unroll
        for (int rr = 0; rr < 8; rr++) {
            if (rA == rr) { m0[rr] = fmaxf(m0[rr], vA.x); m1[rr] = fmaxf(m1[rr], vA.y); }
            if (rB == rr) { m0[rr] = fmaxf(m0[rr], vB.x); m1[rr] = fmaxf(m1[rr], vB.y); }
            if (rC == rr) { m0[rr] = fmaxf(m0[rr], vC.x); m1[rr] = fmaxf(m1[rr], vC.y); }
            if (rD == rr) { m0[rr] = fmaxf(m0[rr], vD.x); m1[rr] = fmaxf(m1[rr], vD.y); }
        }
    }
    for (; e < end; e++) {
        unsigned mc = __ldg(g_meta + e);
        int r = (int)(mc >> 17);
        float2 mv = __half22float2(*(const __half2*)(g_Mh + (size_t)(mc & 0x1FFFFu) * 576 + r * 64 + lane * 2));
        seen |= 1u << r;
#pragma unroll
        for (int rr = 0; rr < 8; rr++) {
            if (r == rr) { m0[rr] = fmaxf(m0[rr], mv.x); m1[rr] = fmaxf(m1[rr], mv.y); }
        }
    }
    float2 tmp = __half22float2(*(const __half2*)(g_Mh + (size_t)gw * 576 + 512 + lane * 2));
    float s0 = tmp.x + __ldg(b2 + lane * 2);
    float s1 = tmp.y + __ldg(b2 + lane * 2 + 1);
#pragma unroll
    for (int rr = 0; rr < 8; rr++) {
        if (seen & (1u << rr)) { s0 += m0[rr]; s1 += m1[rr]; }
    }
    *(float2*)(g_cat + (size_t)gw * 128 + lane * 2) = make_float2(fmaxf(s0, 0.f), fmaxf(s1, 0.f));
}

// ---------------- generic tf32 GEMM (round-13 proven): C fp32 or fp16 ----------------
template <int HOUT>
__global__ void __launch_bounds__(256) k_gemm_tf32(
    const float* __restrict__ A, int lda, int K,
    const float* __restrict__ B, int ldb,
    const float* __restrict__ bias, int relu,
    void* __restrict__ Cout, int ldc, int M)
{
    __shared__ __align__(16) unsigned As[128 * 20];
    __shared__ __align__(16) unsigned Bs[64 * 20];
    int tid = threadIdx.x;
    int wid = tid >> 5, lane = tid & 31;
    int lk = lane & 3;
    int lr = lane >> 2;
    int row0 = blockIdx.x * 128;
    int col0 = blockIdx.y * 64;
    int wm = wid * 16;
    float acc[8][4];
#pragma unroll
    for (int t = 0; t < 8; t++)
#pragma unroll
        for (int i = 0; i < 4; i++) acc[t][i] = 0.f;

    for (int kc = 0; kc < K; kc += 16) {
#pragma unroll
        for (int it = 0; it < 2; it++) {
            int idx = tid + it * 256;
            int r = idx >> 2, kk = (idx & 3) * 4;
            int grow = row0 + r;
            float4 v = (grow < M) ? *(const float4*)(A + (size_t)grow * lda + kc + kk)
                                  : make_float4(0.f, 0.f, 0.f, 0.f);
            uint4 u = make_uint4(f2tf(v.x), f2tf(v.y), f2tf(v.z), f2tf(v.w));
            *(uint4*)&As[r * 20 + kk] = u;
        }
        {
            int r = tid >> 4, cc = (tid & 15) * 4;
            float4 v = *(const float4*)(B + (size_t)(kc + r) * ldb + col0 + cc);
            Bs[(cc + 0) * 20 + r] = f2tf(v.x);
            Bs[(cc + 1) * 20 + r] = f2tf(v.y);
            Bs[(cc + 2) * 20 + r] = f2tf(v.z);
            Bs[(cc + 3) * 20 + r] = f2tf(v.w);
        }
        __syncthreads();
#pragma unroll
        for (int ks = 0; ks < 16; ks += 8) {
            unsigned a0 = As[(wm + lr) * 20 + ks + lk];
            unsigned a1 = As[(wm + 8 + lr) * 20 + ks + lk];
            unsigned a2 = As[(wm + lr) * 20 + ks + 4 + lk];
            unsigned a3 = As[(wm + 8 + lr) * 20 + ks + 4 + lk];
#pragma unroll
            for (int t = 0; t < 8; t++) {
                unsigned b0 = Bs[(t * 8 + lr) * 20 + ks + lk];
                unsigned b1 = Bs[(t * 8 + lr) * 20 + ks + 4 + lk];
                mma_tf32(acc[t][0], acc[t][1], acc[t][2], acc[t][3], a0, a1, a2, a3, b0, b1);
            }
        }
        __syncthreads();
    }
    int r0 = row0 + wm + lr;
    int r1 = r0 + 8;
#pragma unroll
    for (int t = 0; t < 8; t++) {
        int c = col0 + t * 8 + 2 * lk;
        float2 v0 = make_float2(acc[t][0], acc[t][1]);
        float2 v1 = make_float2(acc[t][2], acc[t][3]);
        if (bias) {
            float2 bb = *(const float2*)(bias + (c - col0));
            v0.x += bb.x; v0.y += bb.y; v1.x += bb.x; v1.y += bb.y;
        }
        if (relu) {
            v0.x = fmaxf(v0.x, 0.f); v0.y = fmaxf(v0.y, 0.f);
            v1.x = fmaxf(v1.x, 0.f); v1.y = fmaxf(v1.y, 0.f);
        }
        if (HOUT) {
            __half* C = (__half*)Cout;
            if (r0 < M) *(__half2*)(C + (size_t)r0 * ldc + c) = __floats2half2_rn(v0.x, v0.y);
            if (r1 < M) *(__half2*)(C + (size_t)r1 * ldc + c) = __floats2half2_rn(v1.x, v1.y);
        } else {
            float* C = (float*)Cout;
            if (r0 < M) *(float2*)(C + (size_t)r0 * ldc + c) = v0;
            if (r1 < M) *(float2*)(C + (size_t)r1 * ldc + c) = v1;
        }
    }
}

// ---------------- K=64 specialized M GEMM: Mh[N,576] = h[N,64] @ Wc2[64,576], A staged ONCE ----------------
// 128 threads = 4 warps; tile 64(M) rows; 9 column chunks of 64 reuse the same As.
__global__ void __launch_bounds__(128) k_gemmM(
    const float* __restrict__ A,      // g_h [M,64]
    const float* __restrict__ B,      // g_Wc2 [64,576]
    __half* __restrict__ C, int M)
{
    __shared__ __align__(16) unsigned As[64 * 68];   // [row][k], pad 68 -> (4lr+lk) conflict-free
    __shared__ __align__(16) unsigned Bs[64 * 68];   // [col][k]
    int tid = threadIdx.x;
    int wid = tid >> 5, lane = tid & 31;
    int lk = lane & 3, lr = lane >> 2;
    int row0 = blockIdx.x * 64;
    int wm = wid * 16;

    // stage A once: 64 rows x 64 k = 1024 float4, 8 per thread
#pragma unroll
    for (int it = 0; it < 8; it++) {
        int idx = tid + it * 128;
        int r = idx >> 4, kk = (idx & 15) * 4;
        int grow = row0 + r;
        float4 v = (grow < M) ? *(const float4*)(A + (size_t)grow * 64 + kk)
                              : make_float4(0.f, 0.f, 0.f, 0.f);
        uint4 u = make_uint4(f2tf(v.x), f2tf(v.y), f2tf(v.z), f2tf(v.w));
        *(uint4*)&As[r * 68 + kk] = u;
    }

    for (int cc = 0; cc < 9; cc++) {
        __syncthreads();
        // stage Bs for this 64-col chunk: 64 k x 64 cols = 1024 float4, 8 per thread
#pragma unroll
        for (int it = 0; it < 8; it++) {
            int idx = tid + it * 128;
            int kidx = idx >> 4, c4 = (idx & 15) * 4;
            float4 v = *(const float4*)(B + (size_t)kidx * 576 + cc * 64 + c4);
            Bs[(c4 + 0) * 68 + kidx] = f2tf(v.x);
            Bs[(c4 + 1) * 68 + kidx] = f2tf(v.y);
            Bs[(c4 + 2) * 68 + kidx] = f2tf(v.z);
            Bs[(c4 + 3) * 68 + kidx] = f2tf(v.w);
        }
        __syncthreads();

        float acc[8][4];
#pragma unroll
        for (int t = 0; t < 8; t++)
#pragma unroll
            for (int i = 0; i < 4; i++) acc[t][i] = 0.f;

#pragma unroll
        for (int ks = 0; ks < 64; ks += 8) {
            unsigned a0 = As[(wm + lr) * 68 + ks + lk];
            unsigned a1 = As[(wm + 8 + lr) * 68 + ks + lk];
            unsigned a2 = As[(wm + lr) * 68 + ks + 4 + lk];
            unsigned a3 = As[(wm + 8 + lr) * 68 + ks + 4 + lk];
#pragma unroll
            for (int t = 0; t < 8; t++) {
                unsigned b0 = Bs[(t * 8 + lr) * 68 + ks + lk];
                unsigned b1 = Bs[(t * 8 + lr) * 68 + ks + 4 + lk];
                mma_tf32(acc[t][0], acc[t][1], acc[t][2], acc[t][3], a0, a1, a2, a3, b0, b1);
            }
        }
        int r0 = row0 + wm + lr;
        int r1 = r0 + 8;
#pragma unroll
        for (int t = 0; t < 8; t++) {
            int c = cc * 64 + t * 8 + 2 * lk;
            if (r0 < M) *(__half2*)(C + (size_t)r0 * 576 + c) = __floats2half2_rn(acc[t][0], acc[t][1]);
            if (r1 < M) *(__half2*)(C + (size_t)r1 * 576 + c) = __floats2half2_rn(acc[t][2], acc[t][3]);
        }
    }
}

// ---------------- head: out = tanh(t2 . Wc + bc) * 5 ----------------
__global__ void k_f4(const float* __restrict__ Wc, const float* __restrict__ bc,
                     float* __restrict__ out, int N) {
    int w = (blockIdx.x * blockDim.x + threadIdx.x) >> 5;
    if (w >= N) return;
    int lane = threadIdx.x & 31;
    const float* t = g_t2 + (size_t)w * 64;
    float p = t[lane] * __ldg(Wc + lane) + t[lane + 32] * __ldg(Wc + lane + 32);
#pragma unroll
    for (int off = 16; off > 0; off >>= 1) p += __shfl_xor_sync(0xffffffffu, p, off);
    if (lane == 0) out[w] = tanhf(p + __ldg(bc)) * 5.f;
}

extern "C" void kernel_launch(void* const* d_in, const int* in_sizes, int n_in,
                              void* d_out, int out_size) {
    const float* x      = (const float*)d_in[0];
    const int*   ei     = (const int*)  d_in[1];
    const float* ea     = (const float*)d_in[2];
    const int*   et     = (const int*)  d_in[3];
    const float* omega  = (const float*)d_in[4];
    const float* Wn     = (const float*)d_in[5];
    const float* bn     = (const float*)d_in[6];
    const float* We     = (const float*)d_in[7];
    const float* be     = (const float*)d_in[8];
    const float* Wo     = (const float*)d_in[9];
    const float* bo     = (const float*)d_in[10];
    const float* W1     = (const float*)d_in[11];
    const float* Wroot1 = (const float*)d_in[12];
    const float* b1     = (const float*)d_in[13];
    const float* W2     = (const float*)d_in[14];
    const float* Wroot2 = (const float*)d_in[15];
    const float* b2     = (const float*)d_in[16];
    const float* Wagg   = (const float*)d_in[17];
    const float* bagg   = (const float*)d_in[18];
    const float* Wc     = (const float*)d_in[19];
    const float* bc     = (const float*)d_in[20];
    float* out = (float*)d_out;

    int N = in_sizes[0] / 3;
    int E = in_sizes[3];
    if (N > NMAX) N = NMAX;
    if (E > EMAX) E = EMAX;

    float *pNS, *ph, *pcat, *pt2, *pWc1, *pWc2;
    __half* pMh;
    cudaGetSymbolAddress((void**)&pNS,  g_NS);
    cudaGetSymbolAddress((void**)&ph,   g_h);
    cudaGetSymbolAddress((void**)&pMh,  g_Mh);
    cudaGetSymbolAddress((void**)&pcat, g_cat);
    cudaGetSymbolAddress((void**)&pt2,  g_t2);
    cudaGetSymbolAddress((void**)&pWc1, g_Wc1);
    cudaGetSymbolAddress((void**)&pWc2, g_Wc2);

    // ---- CSR build (round-13 form) ----
    k_zero_cnt<<<(N + 256) / 256, 256>>>(N);
    k_hist<<<(E + 255) / 256, 256>>>(ei, E);
    k_scan<<<1, 1024>>>(N, E);
    k_scatter<<<(E + 255) / 256, 256>>>(ei, ea, et, E);
    // ---- weights + encoders ----
    k_prep<<<(832 * 64 + 255) / 256, 256>>>(Wroot1, W1, W2, Wroot2);
    k_encode<<<(N * 64 + 255) / 256, 256>>>(x, omega, Wn, bn, Wo, bo, N);
    // ---- layer 1 ----
    k_edge1_csr<<<(N * 32 + 255) / 256, 256>>>(We, be, N);
    k_gemm_tf32<0><<<dim3((N + 127) / 128, 1), 256>>>(pNS, 832, 832, pWc1, 64, b1, 1, ph, 64, N);
    // ---- layer 2: K=64 specialized M GEMM (A staged once; the ONE change vs round 13) ----
    k_gemmM<<<(N + 63) / 64, 128>>>(ph, pWc2, pMh, N);
    k_edge2_csr<<<(N * 32 + 255) / 256, 256>>>(b2, N);
    // ---- head (tf32; grid.y = 1) ----
    k_gemm_tf32<0><<<dim3((N + 127) / 128, 1), 256>>>(pcat, 128, 128, Wagg, 64, bagg, 1, pt2, 64, N);
    k_f4<<<(N + 7) / 8, 256>>>(Wc, bc, out, N);
}

// round 17
// speedup vs baseline: 2.5894x; 1.0300x over previous
#include <cuda_runtime.h>
#include <cuda_fp16.h>
#include <cstdint>
#include <cfloat>

#define NMAX 100000
#define EMAX 1600000

// ---------------- scratch (static __device__, allocation-free) ----------------
__device__ float  g_NS[(size_t)NMAX * 832];  // [N][832]: [0:64]=n enc (fp32, GEMM A), [64+r*96..]=S sums
__device__ __half g_nh[(size_t)NMAX * 64];   // n enc in fp16 (edge1 gather source)
__device__ float  g_cat[(size_t)NMAX * 128]; // [N][128]: [0:64]=h2, [64:128]=o enc
__device__ float  g_h[(size_t)NMAX * 64];    // layer-1 output
__device__ __half g_Mh[(size_t)NMAX * 576];  // [N][576] fp16: 0-511 = h@W2[r], 512-575 = h@Wroot2
__device__ float  g_Wc1[832 * 64];           // [Wroot1 ; W1]
__device__ float  g_Wc2[64 * 576];           // [W2^T per-rel | Wroot2]
// CSR (per-dst, round-13 proven)
__device__ int      g_cnt[NMAX + 1];
__device__ int      g_off[NMAX + 1];
__device__ int      g_coff[NMAX + 1];
__device__ unsigned g_meta[EMAX];            // src | (r<<17)
__device__ float2   g_ea2[EMAX];             // edge_attr per sorted slot

// ---------------- tf32 helpers ----------------
__device__ __forceinline__ unsigned f2tf(float f) {
    unsigned u; asm("cvt.rna.tf32.f32 %0, %1;" : "=r"(u) : "f"(f)); return u;
}
__device__ __forceinline__ void mma_tf32(float& c0, float& c1, float& c2, float& c3,
                                         unsigned a0, unsigned a1, unsigned a2, unsigned a3,
                                         unsigned b0, unsigned b1) {
    asm("mma.sync.aligned.m16n8k8.row.col.f32.tf32.tf32.f32 "
        "{%0,%1,%2,%3}, {%4,%5,%6,%7}, {%8,%9}, {%0,%1,%2,%3};"
        : "+f"(c0), "+f"(c1), "+f"(c2), "+f"(c3)
        : "r"(a0), "r"(a1), "r"(a2), "r"(a3), "r"(b0), "r"(b1));
}

// ---------------- CSR build (round-13 proven) ----------------
__global__ void k_zero_cnt(int N) {
    int i = blockIdx.x * 256 + threadIdx.x;
    if (i <= N) g_cnt[i] = 0;
}
__global__ void k_hist(const int* __restrict__ ei, int E) {
    int i = blockIdx.x * 256 + threadIdx.x;
    if (i < E) atomicAdd(&g_cnt[__ldg(ei + E + i)], 1);
}
__global__ void __launch_bounds__(1024) k_scan(int N, int E) {
    __shared__ int sh[1024];
    int t = threadIdx.x;
    int chunk = (N + 1023) / 1024;
    int b = t * chunk, eN = min(b + chunk, N);
    int s = 0;
    for (int i = b; i < eN; i++) s += g_cnt[i];
    sh[t] = s;
    __syncthreads();
    for (int off = 1; off < 1024; off <<= 1) {
        int v = (t >= off) ? sh[t - off] : 0;
        __syncthreads();
        sh[t] += v;
        __syncthreads();
    }
    int run = (t == 0) ? 0 : sh[t - 1];
    for (int i = b; i < eN; i++) {
        int c = g_cnt[i];
        g_off[i] = run; g_coff[i] = run;
        run += c;
    }
    if (t == 0) { g_off[N] = E; g_coff[N] = E; }
}
__global__ void k_scatter(const int* __restrict__ ei, const float* __restrict__ ea,
                          const int* __restrict__ et, int E) {
    int i = blockIdx.x * 256 + threadIdx.x;
    if (i >= E) return;
    int dst = __ldg(ei + E + i);
    int src = __ldg(ei + i);
    int r   = __ldg(et + i);
    int pos = atomicAdd(&g_coff[dst], 1);
    g_meta[pos] = (unsigned)src | ((unsigned)r << 17);
    g_ea2[pos]  = make_float2(__ldg(ea + 2 * i), __ldg(ea + 2 * i + 1));
}

// ---------------- combined weights (832*64 = 53248 threads) ----------------
__global__ void k_prep(const float* __restrict__ Wroot1, const float* __restrict__ W1,
                       const float* __restrict__ W2, const float* __restrict__ Wroot2) {
    int i = blockIdx.x * 256 + threadIdx.x;
    if (i < 832 * 64) {
        int row = i >> 6, j = i & 63;
        g_Wc1[i] = (row < 64) ? Wroot1[row * 64 + j] : W1[(row - 64) * 64 + j];
    }
    if (i < 64 * 576) {
        int k = i / 576, c = i % 576;
        float v;
        if (c < 512) { int r = c >> 6, j = c & 63; v = W2[(r * 64 + k) * 64 + j]; }
        else         { v = Wroot2[k * 64 + (c - 512)]; }
        g_Wc2[i] = v;
    }
}

// ---------------- node encoders (dual write: fp32 for GEMM A, fp16 for edge gather) ----------------
__global__ void k_encode(const float* __restrict__ x, const float* __restrict__ omega,
                         const float* __restrict__ Wn, const float* __restrict__ bn,
                         const float* __restrict__ Wo, const float* __restrict__ bo, int N) {
    int i = blockIdx.x * 256 + threadIdx.x;
    if (i >= N * 64) return;
    int d = i >> 6, j = i & 63;
    float x0 = __ldg(x + d * 3), x1 = __ldg(x + d * 3 + 1), x2 = __ldg(x + d * 3 + 2);
    float nv = fmaf(x0, __ldg(Wn + j), fmaf(x1, __ldg(Wn + 64 + j), fmaf(x2, __ldg(Wn + 128 + j), __ldg(bn + j))));
    nv = fmaxf(nv, 0.f);
    g_NS[(size_t)d * 832 + j] = nv;
    g_nh[(size_t)d * 64 + j] = __float2half_rn(nv);
    float o0 = __ldg(omega + d * 2), o1 = __ldg(omega + d * 2 + 1);
    float ov = fmaf(o0, __ldg(Wo + j), fmaf(o1, __ldg(Wo + 64 + j), __ldg(bo + j)));
    g_cat[(size_t)d * 128 + 64 + j] = fmaxf(ov, 0.f);
}

// ---------------- layer-1: warp per dst; chunk-4 straight-line; fp16 gathers (round-13 proven) ----------------
__global__ void __launch_bounds__(256) k_edge1_csr(const float* __restrict__ We,
                                                   const float* __restrict__ be, int N) {
    int gw = (blockIdx.x * 256 + threadIdx.x) >> 5;
    if (gw >= N) return;
    int lane = threadIdx.x & 31;
    int start = __ldg(g_off + gw), end = __ldg(g_off + gw + 1);

    float we0 = __ldg(We + lane), we1 = __ldg(We + 32 + lane), beL = __ldg(be + lane);
    float an0[8], an1[8], ae[8];
#pragma unroll
    for (int rr = 0; rr < 8; rr++) { an0[rr] = 0.f; an1[rr] = 0.f; ae[rr] = 0.f; }

    int e = start;
    for (; e + 4 <= end; e += 4) {
        unsigned mA = __ldg(g_meta + e),     mB = __ldg(g_meta + e + 1);
        unsigned mC = __ldg(g_meta + e + 2), mD = __ldg(g_meta + e + 3);
        float2 aA = __ldg(g_ea2 + e),     aB = __ldg(g_ea2 + e + 1);
        float2 aC = __ldg(g_ea2 + e + 2), aD = __ldg(g_ea2 + e + 3);
        float2 nA = __half22float2(*(const __half2*)(g_nh + (size_t)(mA & 0x1FFFFu) * 64 + lane * 2));
        float2 nB = __half22float2(*(const __half2*)(g_nh + (size_t)(mB & 0x1FFFFu) * 64 + lane * 2));
        float2 nC = __half22float2(*(const __half2*)(g_nh + (size_t)(mC & 0x1FFFFu) * 64 + lane * 2));
        float2 nD = __half22float2(*(const __half2*)(g_nh + (size_t)(mD & 0x1FFFFu) * 64 + lane * 2));
        float evA = fmaxf(fmaf(aA.x, we0, fmaf(aA.y, we1, beL)), 0.f);
        float evB = fmaxf(fmaf(aB.x, we0, fmaf(aB.y, we1, beL)), 0.f);
        float evC = fmaxf(fmaf(aC.x, we0, fmaf(aC.y, we1, beL)), 0.f);
        float evD = fmaxf(fmaf(aD.x, we0, fmaf(aD.y, we1, beL)), 0.f);
        int rA = (int)(mA >> 17), rB = (int)(mB >> 17);
        int rC = (int)(mC >> 17), rD = (int)(mD >> 17);
#pragma unroll
        for (int rr = 0; rr < 8; rr++) {
            if (rA == rr) { an0[rr] += nA.x; an1[rr] += nA.y; ae[rr] += evA; }
            if (rB == rr) { an0[rr] += nB.x; an1[rr] += nB.y; ae[rr] += evB; }
            if (rC == rr) { an0[rr] += nC.x; an1[rr] += nC.y; ae[rr] += evC; }
            if (rD == rr) { an0[rr] += nD.x; an1[rr] += nD.y; ae[rr] += evD; }
        }
    }
    for (; e < end; e++) {
        unsigned mc = __ldg(g_meta + e);
        float2 ac = __ldg(g_ea2 + e);
        float2 nv = __half22float2(*(const __half2*)(g_nh + (size_t)(mc & 0x1FFFFu) * 64 + lane * 2));
        float ev = fmaxf(fmaf(ac.x, we0, fmaf(ac.y, we1, beL)), 0.f);
        int r = (int)(mc >> 17);
#pragma unroll
        for (int rr = 0; rr < 8; rr++) {
            if (r == rr) { an0[rr] += nv.x; an1[rr] += nv.y; ae[rr] += ev; }
        }
    }
    float* Sd = g_NS + (size_t)gw * 832 + 64;
#pragma unroll
    for (int rr = 0; rr < 8; rr++) {
        *(float2*)(Sd + rr * 96 + lane * 2) = make_float2(an0[rr], an1[rr]);
        Sd[rr * 96 + 64 + lane] = ae[rr];
    }
}

// ---------------- layer-2: warp per dst; chunk-4; fp16 gathers; fused combine (round-13 proven) ----------------
__global__ void __launch_bounds__(256) k_edge2_csr(const float* __restrict__ b2, int N) {
    int gw = (blockIdx.x * 256 + threadIdx.x) >> 5;
    if (gw >= N) return;
    int lane = threadIdx.x & 31;
    int start = __ldg(g_off + gw), end = __ldg(g_off + gw + 1);

    float m0[8], m1[8];
#pragma unroll
    for (int rr = 0; rr < 8; rr++) { m0[rr] = -FLT_MAX; m1[rr] = -FLT_MAX; }
    unsigned seen = 0;

    int e = start;
    for (; e + 4 <= end; e += 4) {
        unsigned mA = __ldg(g_meta + e),     mB = __ldg(g_meta + e + 1);
        unsigned mC = __ldg(g_meta + e + 2), mD = __ldg(g_meta + e + 3);
        int rA = (int)(mA >> 17), rB = (int)(mB >> 17);
        int rC = (int)(mC >> 17), rD = (int)(mD >> 17);
        float2 vA = __half22float2(*(const __half2*)(g_Mh + (size_t)(mA & 0x1FFFFu) * 576 + rA * 64 + lane * 2));
        float2 vB = __half22float2(*(const __half2*)(g_Mh + (size_t)(mB & 0x1FFFFu) * 576 + rB * 64 + lane * 2));
        float2 vC = __half22float2(*(const __half2*)(g_Mh + (size_t)(mC & 0x1FFFFu) * 576 + rC * 64 + lane * 2));
        float2 vD = __half22float2(*(const __half2*)(g_Mh + (size_t)(mD & 0x1FFFFu) * 576 + rD * 64 + lane * 2));
        seen |= (1u << rA) | (1u << rB) | (1u << rC) | (1u << rD);
#pragma unroll
        for (int rr = 0; rr < 8; rr++) {
            if (rA == rr) { m0[rr] = fmaxf(m0[rr], vA.x); m1[rr] = fmaxf(m1[rr], vA.y); }
            if (rB == rr) { m0[rr] = fmaxf(m0[rr], vB.x); m1[rr] = fmaxf(m1[rr], vB.y); }
            if (rC == rr) { m0[rr] = fmaxf(m0[rr], vC.x); m1[rr] = fmaxf(m1[rr], vC.y); }
            if (rD == rr) { m0[rr] = fmaxf(m0[rr], vD.x); m1[rr] = fmaxf(m1[rr], vD.y); }
        }
    }
    for (; e < end; e++) {
        unsigned mc = __ldg(g_meta + e);
        int r = (int)(mc >> 17);
        float2 mv = __half22float2(*(const __half2*)(g_Mh + (size_t)(mc & 0x1FFFFu) * 576 + r * 64 + lane * 2));
        seen |= 1u << r;
#pragma unroll
        for (int rr = 0; rr < 8; rr++) {
            if (r == rr) { m0[rr] = fmaxf(m0[rr], mv.x); m1[rr] = fmaxf(m1[rr], mv.y); }
        }
    }
    float2 tmp = __half22float2(*(const __half2*)(g_Mh + (size_t)gw * 576 + 512 + lane * 2));
    float s0 = tmp.x + __ldg(b2 + lane * 2);
    float s1 = tmp.y + __ldg(b2 + lane * 2 + 1);
#pragma unroll
    for (int rr = 0; rr < 8; rr++) {
        if (seen & (1u << rr)) { s0 += m0[rr]; s1 += m1[rr]; }
    }
    *(float2*)(g_cat + (size_t)gw * 128 + lane * 2) = make_float2(fmaxf(s0, 0.f), fmaxf(s1, 0.f));
}

// ---------------- generic tf32 GEMM (round-13 proven): C fp32 or fp16 ----------------
template <int HOUT>
__global__ void __launch_bounds__(256) k_gemm_tf32(
    const float* __restrict__ A, int lda, int K,
    const float* __restrict__ B, int ldb,
    const float* __restrict__ bias, int relu,
    void* __restrict__ Cout, int ldc, int M)
{
    __shared__ __align__(16) unsigned As[128 * 20];
    __shared__ __align__(16) unsigned Bs[64 * 20];
    int tid = threadIdx.x;
    int wid = tid >> 5, lane = tid & 31;
    int lk = lane & 3;
    int lr = lane >> 2;
    int row0 = blockIdx.x * 128;
    int col0 = blockIdx.y * 64;
    int wm = wid * 16;
    float acc[8][4];
#pragma unroll
    for (int t = 0; t < 8; t++)
#pragma unroll
        for (int i = 0; i < 4; i++) acc[t][i] = 0.f;

    for (int kc = 0; kc < K; kc += 16) {
#pragma unroll
        for (int it = 0; it < 2; it++) {
            int idx = tid + it * 256;
            int r = idx >> 2, kk = (idx & 3) * 4;
            int grow = row0 + r;
            float4 v = (grow < M) ? *(const float4*)(A + (size_t)grow * lda + kc + kk)
                                  : make_float4(0.f, 0.f, 0.f, 0.f);
            uint4 u = make_uint4(f2tf(v.x), f2tf(v.y), f2tf(v.z), f2tf(v.w));
            *(uint4*)&As[r * 20 + kk] = u;
        }
        {
            int r = tid >> 4, cc = (tid & 15) * 4;
            float4 v = *(const float4*)(B + (size_t)(kc + r) * ldb + col0 + cc);
            Bs[(cc + 0) * 20 + r] = f2tf(v.x);
            Bs[(cc + 1) * 20 + r] = f2tf(v.y);
            Bs[(cc + 2) * 20 + r] = f2tf(v.z);
            Bs[(cc + 3) * 20 + r] = f2tf(v.w);
        }
        __syncthreads();
#pragma unroll
        for (int ks = 0; ks < 16; ks += 8) {
            unsigned a0 = As[(wm + lr) * 20 + ks + lk];
            unsigned a1 = As[(wm + 8 + lr) * 20 + ks + lk];
            unsigned a2 = As[(wm + lr) * 20 + ks + 4 + lk];
            unsigned a3 = As[(wm + 8 + lr) * 20 + ks + 4 + lk];
#pragma unroll
            for (int t = 0; t < 8; t++) {
                unsigned b0 = Bs[(t * 8 + lr) * 20 + ks + lk];
                unsigned b1 = Bs[(t * 8 + lr) * 20 + ks + 4 + lk];
                mma_tf32(acc[t][0], acc[t][1], acc[t][2], acc[t][3], a0, a1, a2, a3, b0, b1);
            }
        }
        __syncthreads();
    }
    int r0 = row0 + wm + lr;
    int r1 = r0 + 8;
#pragma unroll
    for (int t = 0; t < 8; t++) {
        int c = col0 + t * 8 + 2 * lk;
        float2 v0 = make_float2(acc[t][0], acc[t][1]);
        float2 v1 = make_float2(acc[t][2], acc[t][3]);
        if (bias) {
            float2 bb = *(const float2*)(bias + (c - col0));
            v0.x += bb.x; v0.y += bb.y; v1.x += bb.x; v1.y += bb.y;
        }
        if (relu) {
            v0.x = fmaxf(v0.x, 0.f); v0.y = fmaxf(v0.y, 0.f);
            v1.x = fmaxf(v1.x, 0.f); v1.y = fmaxf(v1.y, 0.f);
        }
        if (HOUT) {
            __half* C = (__half*)Cout;
            if (r0 < M) *(__half2*)(C + (size_t)r0 * ldc + c) = __floats2half2_rn(v0.x, v0.y);
            if (r1 < M) *(__half2*)(C + (size_t)r1 * ldc + c) = __floats2half2_rn(v1.x, v1.y);
        } else {
            float* C = (float*)Cout;
            if (r0 < M) *(float2*)(C + (size_t)r0 * ldc + c) = v0;
            if (r1 < M) *(float2*)(C + (size_t)r1 * ldc + c) = v1;
        }
    }
}

// ---------------- fused head: out = tanh(relu(cat @ Wagg + bagg) . Wc + bc) * 5 ----------------
// Same tile/fragment layout as k_gemm_tf32 (K=128, 64 cols); epilogue dots with Wc and reduces over lk.
__global__ void __launch_bounds__(256) k_head(
    const float* __restrict__ A,      // g_cat [M,128]
    const float* __restrict__ B,      // Wagg [128,64]
    const float* __restrict__ bias,   // bagg
    const float* __restrict__ Wc, const float* __restrict__ bc,
    float* __restrict__ out, int M)
{
    __shared__ __align__(16) unsigned As[128 * 20];
    __shared__ __align__(16) unsigned Bs[64 * 20];
    int tid = threadIdx.x;
    int wid = tid >> 5, lane = tid & 31;
    int lk = lane & 3;
    int lr = lane >> 2;
    int row0 = blockIdx.x * 128;
    int wm = wid * 16;
    float acc[8][4];
#pragma unroll
    for (int t = 0; t < 8; t++)
#pragma unroll
        for (int i = 0; i < 4; i++) acc[t][i] = 0.f;

    for (int kc = 0; kc < 128; kc += 16) {
#pragma unroll
        for (int it = 0; it < 2; it++) {
            int idx = tid + it * 256;
            int r = idx >> 2, kk = (idx & 3) * 4;
            int grow = row0 + r;
            float4 v = (grow < M) ? *(const float4*)(A + (size_t)grow * 128 + kc + kk)
                                  : make_float4(0.f, 0.f, 0.f, 0.f);
            uint4 u = make_uint4(f2tf(v.x), f2tf(v.y), f2tf(v.z), f2tf(v.w));
            *(uint4*)&As[r * 20 + kk] = u;
        }
        {
            int r = tid >> 4, cc = (tid & 15) * 4;
            float4 v = *(const float4*)(B + (size_t)(kc + r) * 64 + cc);
            Bs[(cc + 0) * 20 + r] = f2tf(v.x);
            Bs[(cc + 1) * 20 + r] = f2tf(v.y);
            Bs[(cc + 2) * 20 + r] = f2tf(v.z);
            Bs[(cc + 3) * 20 + r] = f2tf(v.w);
        }
        __syncthreads();
#pragma unroll
        for (int ks = 0; ks < 16; ks += 8) {
            unsigned a0 = As[(wm + lr) * 20 + ks + lk];
            unsigned a1 = As[(wm + 8 + lr) * 20 + ks + lk];
            unsigned a2 = As[(wm + lr) * 20 + ks + 4 + lk];
            unsigned a3 = As[(wm + 8 + lr) * 20 + ks + 4 + lk];
#pragma unroll
            for (int t = 0; t < 8; t++) {
                unsigned b0 = Bs[(t * 8 + lr) * 20 + ks + lk];
                unsigned b1 = Bs[(t * 8 + lr) * 20 + ks + 4 + lk];
                mma_tf32(acc[t][0], acc[t][1], acc[t][2], acc[t][3], a0, a1, a2, a3, b0, b1);
            }
        }
        __syncthreads();
    }
    // epilogue: relu + dot Wc across this thread's 16 cols, then reduce over the 4 lk-lanes
    float part0 = 0.f, part1 = 0.f;
#pragma unroll
    for (int t = 0; t < 8; t++) {
        int c = t * 8 + 2 * lk;
        float2 bb = *(const float2*)(bias + c);
        float2 wc = *(const float2*)(Wc + c);
        float v0 = fmaxf(acc[t][0] + bb.x, 0.f);
        float v1 = fmaxf(acc[t][1] + bb.y, 0.f);
        float v2 = fmaxf(acc[t][2] + bb.x, 0.f);
        float v3 = fmaxf(acc[t][3] + bb.y, 0.f);
        part0 += v0 * wc.x + v1 * wc.y;
        part1 += v2 * wc.x + v3 * wc.y;
    }
    part0 += __shfl_xor_sync(0xffffffffu, part0, 1);
    part0 += __shfl_xor_sync(0xffffffffu, part0, 2);
    part1 += __shfl_xor_sync(0xffffffffu, part1, 1);
    part1 += __shfl_xor_sync(0xffffffffu, part1, 2);
    int r0 = row0 + wm + lr;
    int r1 = r0 + 8;
    if (lk == 0) {
        float bcv = __ldg(bc);
        if (r0 < M) out[r0] = tanhf(part0 + bcv) * 5.f;
        if (r1 < M) out[r1] = tanhf(part1 + bcv) * 5.f;
    }
}

extern "C" void kernel_launch(void* const* d_in, const int* in_sizes, int n_in,
                              void* d_out, int out_size) {
    const float* x      = (const float*)d_in[0];
    const int*   ei     = (const int*)  d_in[1];
    const float* ea     = (const float*)d_in[2];
    const int*   et     = (const int*)  d_in[3];
    const float* omega  = (const float*)d_in[4];
    const float* Wn     = (const float*)d_in[5];
    const float* bn     = (const float*)d_in[6];
    const float* We     = (const float*)d_in[7];
    const float* be     = (const float*)d_in[8];
    const float* Wo     = (const float*)d_in[9];
    const float* bo     = (const float*)d_in[10];
    const float* W1     = (const float*)d_in[11];
    const float* Wroot1 = (const float*)d_in[12];
    const float* b1     = (const float*)d_in[13];
    const float* W2     = (const float*)d_in[14];
    const float* Wroot2 = (const float*)d_in[15];
    const float* b2     = (const float*)d_in[16];
    const float* Wagg   = (const float*)d_in[17];
    const float* bagg   = (const float*)d_in[18];
    const float* Wc     = (const float*)d_in[19];
    const float* bc     = (const float*)d_in[20];
    float* out = (float*)d_out;

    int N = in_sizes[0] / 3;
    int E = in_sizes[3];
    if (N > NMAX) N = NMAX;
    if (E > EMAX) E = EMAX;

    float *pNS, *ph, *pcat, *pWc1, *pWc2;
    __half* pMh;
    cudaGetSymbolAddress((void**)&pNS,  g_NS);
    cudaGetSymbolAddress((void**)&ph,   g_h);
    cudaGetSymbolAddress((void**)&pMh,  g_Mh);
    cudaGetSymbolAddress((void**)&pcat, g_cat);
    cudaGetSymbolAddress((void**)&pWc1, g_Wc1);
    cudaGetSymbolAddress((void**)&pWc2, g_Wc2);

    // side stream + fork/join events (created on the first, uncaptured, correctness call)
    static cudaStream_t s2 = nullptr;
    static cudaEvent_t evF = nullptr, evJ = nullptr;
    if (!s2) {
        cudaStreamCreateWithFlags(&s2, cudaStreamNonBlocking);
        cudaEventCreateWithFlags(&evF, cudaEventDisableTiming);
        cudaEventCreateWithFlags(&evJ, cudaEventDisableTiming);
    }

    // ---- fork: encode + prep on side stream, overlapped with CSR chain ----
    cudaEventRecord(evF, 0);
    cudaStreamWaitEvent(s2, evF, 0);
    k_encode<<<(N * 64 + 255) / 256, 256, 0, s2>>>(x, omega, Wn, bn, Wo, bo, N);
    k_prep<<<(832 * 64 + 255) / 256, 256, 0, s2>>>(Wroot1, W1, W2, Wroot2);
    cudaEventRecord(evJ, s2);

    // ---- CSR build on main stream ----
    k_zero_cnt<<<(N + 256) / 256, 256>>>(N);
    k_hist<<<(E + 255) / 256, 256>>>(ei, E);
    k_scan<<<1, 1024>>>(N, E);
    k_scatter<<<(E + 255) / 256, 256>>>(ei, ea, et, E);
    cudaStreamWaitEvent(0, evJ, 0);   // join before edge1/gemm1

    // ---- layer 1 ----
    k_edge1_csr<<<(N * 32 + 255) / 256, 256>>>(We, be, N);
    k_gemm_tf32<0><<<dim3((N + 127) / 128, 1), 256>>>(pNS, 832, 832, pWc1, 64, b1, 1, ph, 64, N);
    // ---- layer 2 (M written as fp16; round-13 generic GEMM) ----
    k_gemm_tf32<1><<<dim3((N + 127) / 128, 9), 256>>>(ph, 64, 64, pWc2, 576, nullptr, 0, pMh, 576, N);
    k_edge2_csr<<<(N * 32 + 255) / 256, 256>>>(b2, N);
    // ---- fused head (GEMM + f4 in one) ----
    k_head<<<(N + 127) / 128, 256>>>(pcat, Wagg, bagg, Wc, bc, out, N);
}